// round 3
// baseline (speedup 1.0000x reference)
#include <cuda_runtime.h>
#include <math.h>

// ----------------------------------------------------------------------------
// LinearAttentionBlock: out = ((phi(xWq+bq) @ phi(xWk+bk)^T masked) @ (xWv+bv))
//                              / rowsum  @ Wo + bo
// B=4, N=2048, d_model=1024, d_inner=2048. All fp32.
// Decomposition: 3 proj GEMMs -> masked NT GEMM (lower-tri only) -> rowsum ->
//                truncated NN GEMM with divide epilogue -> output GEMM.
// ----------------------------------------------------------------------------

#define BM 128
#define BN 128
#define BK 16
#define TM 8
#define TN 8

#define BATCH 4
#define SEQ   2048
#define DM    1024
#define DI    2048

// Scratch (allocation-free rule: __device__ globals)
__device__ __align__(16) float g_Q[BATCH * SEQ * DI];
__device__ __align__(16) float g_K[BATCH * SEQ * DI];
__device__ __align__(16) float g_V[BATCH * SEQ * DI];
__device__ __align__(16) float g_S[BATCH * SEQ * SEQ];
__device__ __align__(16) float g_O[BATCH * SEQ * DI];
__device__ __align__(16) float g_den[BATCH * SEQ];

__device__ __forceinline__ float phi_act(float v) {
    // elu(v) + 1:  v>0 -> v+1 ; else exp(v)
    return v > 0.f ? v + 1.f : __expf(v);
}

// ---------------------------------------------------------------------------
// Generic NN SGEMM: C[M,N] = A[M,K] @ B[K,N] + bias[N], optional phi epilogue.
// Requires M%128==0, N%128==0, K%16==0. 256 threads, 8x8 per thread.
// ---------------------------------------------------------------------------
template <int ACT>
__global__ __launch_bounds__(256) void sgemm_nn(
    const float* __restrict__ A, const float* __restrict__ B,
    const float* __restrict__ bias, float* __restrict__ C,
    int M, int N, int K)
{
    __shared__ float As[BK][BM];
    __shared__ float Bs[BK][BN];
    const int tid = threadIdx.x;
    const int tx = tid & 15;
    const int ty = tid >> 4;
    const int rowBase = blockIdx.y * BM;
    const int colBase = blockIdx.x * BN;

    float acc[TM][TN];
#pragma unroll
    for (int i = 0; i < TM; i++)
#pragma unroll
        for (int j = 0; j < TN; j++) acc[i][j] = 0.f;

    for (int kt = 0; kt < K; kt += BK) {
#pragma unroll
        for (int l = 0; l < 2; l++) {
            int i = tid + l * 256;           // 512 float4 for A tile
            int r = i >> 2;
            int c4 = (i & 3) * 4;
            float4 f = *(const float4*)(A + (size_t)(rowBase + r) * K + kt + c4);
            As[c4 + 0][r] = f.x; As[c4 + 1][r] = f.y;
            As[c4 + 2][r] = f.z; As[c4 + 3][r] = f.w;
        }
#pragma unroll
        for (int l = 0; l < 2; l++) {
            int i = tid + l * 256;           // 512 float4 for B tile
            int r = i >> 5;
            int c4 = (i & 31) * 4;
            *(float4*)&Bs[r][c4] =
                *(const float4*)(B + (size_t)(kt + r) * N + colBase + c4);
        }
        __syncthreads();
#pragma unroll
        for (int k = 0; k < BK; k++) {
            float a[TM], b[TN];
#pragma unroll
            for (int i = 0; i < TM; i++) a[i] = As[k][ty * TM + i];
#pragma unroll
            for (int j = 0; j < TN; j++) b[j] = Bs[k][tx * TN + j];
#pragma unroll
            for (int i = 0; i < TM; i++)
#pragma unroll
                for (int j = 0; j < TN; j++)
                    acc[i][j] = fmaf(a[i], b[j], acc[i][j]);
        }
        __syncthreads();
    }

#pragma unroll
    for (int i = 0; i < TM; i++) {
        int row = rowBase + ty * TM + i;
#pragma unroll
        for (int j = 0; j < TN; j++) {
            int col = colBase + tx * TN + j;
            float v = acc[i][j] + bias[col];
            if (ACT == 1) v = phi_act(v);
            C[(size_t)row * N + col] = v;
        }
    }
}

// ---------------------------------------------------------------------------
// Scores: S[b][n][m] = sum_d Q[b][n][d]*K[b][m][d], m<=n only (causal).
// NT GEMM per batch. Upper-triangle blocks skipped entirely (never read later).
// Diagonal block masked to exact 0 above the diagonal.
// ---------------------------------------------------------------------------
__global__ __launch_bounds__(256) void sgemm_nt_scores(
    const float* __restrict__ Qg, const float* __restrict__ Kg,
    float* __restrict__ Sg)
{
    const int bx = blockIdx.x;   // key block (m)
    const int by = blockIdx.y;   // query block (n)
    if (bx > by) return;         // strictly upper: never written, never read
    const int b = blockIdx.z;

    const float* A = Qg + (size_t)b * SEQ * DI;
    const float* B = Kg + (size_t)b * SEQ * DI;
    float* C = Sg + (size_t)b * SEQ * SEQ;

    __shared__ float As[BK][BM];
    __shared__ float Bs[BK][BN];
    const int tid = threadIdx.x;
    const int tx = tid & 15;
    const int ty = tid >> 4;
    const int rowBase = by * BM;
    const int colBase = bx * BN;

    float acc[TM][TN];
#pragma unroll
    for (int i = 0; i < TM; i++)
#pragma unroll
        for (int j = 0; j < TN; j++) acc[i][j] = 0.f;

    for (int kt = 0; kt < DI; kt += BK) {
#pragma unroll
        for (int l = 0; l < 2; l++) {
            int i = tid + l * 256;
            int r = i >> 2;
            int c4 = (i & 3) * 4;
            float4 f = *(const float4*)(A + (size_t)(rowBase + r) * DI + kt + c4);
            As[c4 + 0][r] = f.x; As[c4 + 1][r] = f.y;
            As[c4 + 2][r] = f.z; As[c4 + 3][r] = f.w;
        }
#pragma unroll
        for (int l = 0; l < 2; l++) {
            int i = tid + l * 256;           // key row = colBase+mm, dim = kt+d4
            int mm = i >> 2;
            int d4 = (i & 3) * 4;
            float4 f = *(const float4*)(B + (size_t)(colBase + mm) * DI + kt + d4);
            Bs[d4 + 0][mm] = f.x; Bs[d4 + 1][mm] = f.y;
            Bs[d4 + 2][mm] = f.z; Bs[d4 + 3][mm] = f.w;
        }
        __syncthreads();
#pragma unroll
        for (int k = 0; k < BK; k++) {
            float a[TM], bb[TN];
#pragma unroll
            for (int i = 0; i < TM; i++) a[i] = As[k][ty * TM + i];
#pragma unroll
            for (int j = 0; j < TN; j++) bb[j] = Bs[k][tx * TN + j];
#pragma unroll
            for (int i = 0; i < TM; i++)
#pragma unroll
                for (int j = 0; j < TN; j++)
                    acc[i][j] = fmaf(a[i], bb[j], acc[i][j]);
        }
        __syncthreads();
    }

    const bool diag = (bx == by);
#pragma unroll
    for (int i = 0; i < TM; i++) {
        int row = rowBase + ty * TM + i;
#pragma unroll
        for (int j = 0; j < TN; j++) {
            int col = colBase + tx * TN + j;
            float v = acc[i][j];
            if (diag && col > row) v = 0.f;
            C[(size_t)row * SEQ + col] = v;
        }
    }
}

// ---------------------------------------------------------------------------
// Denominator: den[b][n] = EPS + sum_{m written} S[b][n][m]
// (upper part of diagonal block is exact 0, so summing the written region
//  [0, (n/128+1)*128) equals the masked sum). One 256-thread block per row.
// ---------------------------------------------------------------------------
__global__ __launch_bounds__(256) void rowsum_k(
    const float* __restrict__ Sg, float* __restrict__ den)
{
    const int row = blockIdx.x;          // 0 .. BATCH*SEQ-1
    const int b = row >> 11;
    const int n = row & (SEQ - 1);
    const float* sr = Sg + ((size_t)b * SEQ + n) * SEQ;
    const int mlim = ((n >> 7) + 1) << 7;

    float s = 0.f;
    for (int m = threadIdx.x; m < mlim; m += 256) s += sr[m];

    __shared__ float red[256];
    red[threadIdx.x] = s;
    __syncthreads();
#pragma unroll
    for (int o = 128; o > 0; o >>= 1) {
        if (threadIdx.x < o) red[threadIdx.x] += red[threadIdx.x + o];
        __syncthreads();
    }
    if (threadIdx.x == 0) den[row] = red[0] + 1e-6f;
}

// ---------------------------------------------------------------------------
// O[b] = (S[b] @ V[b]) / den[b][row].  K-loop truncated at the diagonal:
// for query block by, only m < (by+1)*128 can be nonzero.
// ---------------------------------------------------------------------------
__global__ __launch_bounds__(256) void sgemm_av(
    const float* __restrict__ Sg, const float* __restrict__ Vg,
    const float* __restrict__ den, float* __restrict__ Og)
{
    const int b = blockIdx.z;
    const float* A = Sg + (size_t)b * SEQ * SEQ;
    const float* B = Vg + (size_t)b * SEQ * DI;
    float* C = Og + (size_t)b * SEQ * DI;

    __shared__ float As[BK][BM];
    __shared__ float Bs[BK][BN];
    const int tid = threadIdx.x;
    const int tx = tid & 15;
    const int ty = tid >> 4;
    const int rowBase = blockIdx.y * BM;
    const int colBase = blockIdx.x * BN;
    const int Klim = (blockIdx.y + 1) * BM;   // causal truncation

    float acc[TM][TN];
#pragma unroll
    for (int i = 0; i < TM; i++)
#pragma unroll
        for (int j = 0; j < TN; j++) acc[i][j] = 0.f;

    for (int kt = 0; kt < Klim; kt += BK) {
#pragma unroll
        for (int l = 0; l < 2; l++) {
            int i = tid + l * 256;
            int r = i >> 2;
            int c4 = (i & 3) * 4;
            float4 f = *(const float4*)(A + (size_t)(rowBase + r) * SEQ + kt + c4);
            As[c4 + 0][r] = f.x; As[c4 + 1][r] = f.y;
            As[c4 + 2][r] = f.z; As[c4 + 3][r] = f.w;
        }
#pragma unroll
        for (int l = 0; l < 2; l++) {
            int i = tid + l * 256;
            int r = i >> 5;
            int c4 = (i & 31) * 4;
            *(float4*)&Bs[r][c4] =
                *(const float4*)(B + (size_t)(kt + r) * DI + colBase + c4);
        }
        __syncthreads();
#pragma unroll
        for (int k = 0; k < BK; k++) {
            float a[TM], bb[TN];
#pragma unroll
            for (int i = 0; i < TM; i++) a[i] = As[k][ty * TM + i];
#pragma unroll
            for (int j = 0; j < TN; j++) bb[j] = Bs[k][tx * TN + j];
#pragma unroll
            for (int i = 0; i < TM; i++)
#pragma unroll
                for (int j = 0; j < TN; j++)
                    acc[i][j] = fmaf(a[i], bb[j], acc[i][j]);
        }
        __syncthreads();
    }

#pragma unroll
    for (int i = 0; i < TM; i++) {
        int row = rowBase + ty * TM + i;
        float inv = 1.f / den[b * SEQ + row];
#pragma unroll
        for (int j = 0; j < TN; j++) {
            int col = colBase + tx * TN + j;
            C[(size_t)row * DI + col] = acc[i][j] * inv;
        }
    }
}

// ---------------------------------------------------------------------------
extern "C" void kernel_launch(void* const* d_in, const int* in_sizes, int n_in,
                              void* d_out, int out_size)
{
    const float* x  = (const float*)d_in[0];
    const float* Wq = (const float*)d_in[1];
    const float* bq = (const float*)d_in[2];
    const float* Wk = (const float*)d_in[3];
    const float* bk = (const float*)d_in[4];
    const float* Wv = (const float*)d_in[5];
    const float* bv = (const float*)d_in[6];
    const float* Wo = (const float*)d_in[7];
    const float* bo = (const float*)d_in[8];
    float* out = (float*)d_out;

    float *Qp, *Kp, *Vp, *Sp, *Op, *dp;
    cudaGetSymbolAddress((void**)&Qp, g_Q);
    cudaGetSymbolAddress((void**)&Kp, g_K);
    cudaGetSymbolAddress((void**)&Vp, g_V);
    cudaGetSymbolAddress((void**)&Sp, g_S);
    cudaGetSymbolAddress((void**)&Op, g_O);
    cudaGetSymbolAddress((void**)&dp, g_den);

    const int M = BATCH * SEQ;                 // 8192

    // Q/K/V projections (fused bias + phi for Q,K)
    dim3 gproj(DI / BN, M / BM);               // (16, 64)
    sgemm_nn<1><<<gproj, 256>>>(x, Wq, bq, Qp, M, DI, DM);
    sgemm_nn<1><<<gproj, 256>>>(x, Wk, bk, Kp, M, DI, DM);
    sgemm_nn<0><<<gproj, 256>>>(x, Wv, bv, Vp, M, DI, DM);

    // Causal scores (lower-triangle blocks only)
    dim3 gsc(SEQ / BN, SEQ / BM, BATCH);       // (16, 16, 4)
    sgemm_nt_scores<<<gsc, 256>>>(Qp, Kp, Sp);

    // Denominators
    rowsum_k<<<BATCH * SEQ, 256>>>(Sp, dp);

    // (S @ V) / den
    dim3 gav(DI / BN, SEQ / BM, BATCH);        // (16, 16, 4)
    sgemm_av<<<gav, 256>>>(Sp, Vp, dp, Op);

    // Output projection
    dim3 gout(DM / BN, M / BM);                // (8, 64)
    sgemm_nn<0><<<gout, 256>>>(Op, Wo, bo, out, M, DM, DI);
}

// round 7
// speedup vs baseline: 3.0376x; 3.0376x over previous
#include <cuda_runtime.h>
#include <cstdint>
#include <math.h>

#define BATCH 4
#define SEQ   2048
#define DM    1024
#define DI    2048
#define NSTG  3
// A tile: 128 rows x 36 floats (32 K + 4 pad), B same. One stage:
#define ROWSTRIDE 36
#define AMAT_BYTES (128 * ROWSTRIDE * 4)      // 18432
#define STAGE (2 * AMAT_BYTES)                // 36864

__device__ __align__(16) float g_xr [BATCH * SEQ * DM];
__device__ __align__(16) float g_Wqt[DI * DM];
__device__ __align__(16) float g_Wkt[DI * DM];
__device__ __align__(16) float g_Wvt[DI * DM];
__device__ __align__(16) float g_Wot[DM * DI];
__device__ __align__(16) float g_Q  [BATCH * SEQ * DI];
__device__ __align__(16) float g_K  [BATCH * SEQ * DI];
__device__ __align__(16) float g_Vt [BATCH * DI * SEQ];
__device__ __align__(16) float g_S  [BATCH * SEQ * SEQ];
__device__ __align__(16) float g_O  [BATCH * SEQ * DI];
__device__ float g_den[BATCH * SEQ];

__device__ __forceinline__ float rna(float x) {
    uint32_t r;
    asm("cvt.rna.tf32.f32 %0, %1;" : "=r"(r) : "f"(x));
    return __uint_as_float(r);
}
__device__ __forceinline__ float phi_act(float v) { return v > 0.f ? v + 1.f : __expf(v); }

#define MMA_TF32(d, a, b)                                                     \
    asm volatile("mma.sync.aligned.m16n8k8.row.col.f32.tf32.tf32.f32 "        \
                 "{%0,%1,%2,%3}, {%4,%5,%6,%7}, {%8,%9}, {%0,%1,%2,%3};"      \
                 : "+f"((d)[0]), "+f"((d)[1]), "+f"((d)[2]), "+f"((d)[3])     \
                 : "r"((a)[0]), "r"((a)[1]), "r"((a)[2]), "r"((a)[3]),        \
                   "r"((b)[0]), "r"((b)[1]))

// ------------------------------- prep kernels -------------------------------
__global__ __launch_bounds__(256) void rna_copy4(
    const float4* __restrict__ in, float4* __restrict__ out, int n4)
{
    int i = blockIdx.x * 256 + threadIdx.x;
    if (i < n4) {
        float4 v = in[i];
        v.x = rna(v.x); v.y = rna(v.y); v.z = rna(v.z); v.w = rna(v.w);
        out[i] = v;
    }
}
// out[C,R] = rna(in[R,C]^T); grid (C/32, R/32), block (32,8)
__global__ __launch_bounds__(256) void transpose_rna(
    const float* __restrict__ in, float* __restrict__ out, int R, int C)
{
    __shared__ float t[32][33];
    int bx = blockIdx.x * 32, by = blockIdx.y * 32;
    int tx = threadIdx.x, ty = threadIdx.y;
#pragma unroll
    for (int j = 0; j < 32; j += 8)
        t[ty + j][tx] = in[(size_t)(by + ty + j) * C + bx + tx];
    __syncthreads();
#pragma unroll
    for (int j = 0; j < 32; j += 8)
        out[(size_t)(bx + ty + j) * R + by + tx] = rna(t[tx][ty + j]);
}

__global__ __launch_bounds__(256) void rowsum_k(
    const float* __restrict__ Sg, float* __restrict__ den)
{
    const int row = blockIdx.x;
    const int b = row >> 11, n = row & (SEQ - 1);
    const float* sr = Sg + ((size_t)b * SEQ + n) * SEQ;
    const int mlim = ((n >> 7) + 1) << 7;
    float s = 0.f;
    for (int m = threadIdx.x; m < mlim; m += 256) s += sr[m];
    __shared__ float red[256];
    red[threadIdx.x] = s;
    __syncthreads();
#pragma unroll
    for (int o = 128; o > 0; o >>= 1) {
        if (threadIdx.x < o) red[threadIdx.x] += red[threadIdx.x + o];
        __syncthreads();
    }
    if (threadIdx.x == 0) den[row] = red[0] + 1e-6f;
}

// ============================================================================
// tf32 mma.sync NT GEMM: C[M,N] = A[M,K]@B[N,K]^T + epilogue. Tile 128x128x32.
// 8 warps, each 64x32 (4x4 m16n8k8 tiles). 3-stage cp.async pipeline.
// EPI: 0=bias+phi+rna  1=bias+rna,V^T store  2=causal+rna  3=/den+rna  4=bias
// ============================================================================
template <int EPI>
__global__ __launch_bounds__(256, 1) void gemm_tc(
    const float* __restrict__ Ab, const float* __restrict__ Bb,
    const float* __restrict__ bias, const float* __restrict__ den,
    float* __restrict__ Cb,
    int lda, int ldb, int ldc, int Kfull, long aB, long bB, long cB)
{
    const int bx = blockIdx.x, by = blockIdx.y, bz = blockIdx.z;
    if (EPI == 2 && bx > by) return;
    const int rowBase = by * 128, colBase = bx * 128;
    const int Klen = (EPI == 3) ? (by + 1) * 128 : Kfull;
    const int iters = Klen >> 5;                     // >= 4 always

    const float* A = Ab + (size_t)bz * aB;
    const float* B = Bb + (size_t)bz * bB;

    extern __shared__ char dynsm[];
    const int tid = threadIdx.x;
    const int lane = tid & 31, wid = tid >> 5;
    const int wr = wid & 1, wc = wid >> 1;           // warp 64x32 tile

    // ---- async tile loader: A rows then B rows, 16B chunks, padded stride
    auto load_stage = [&](int p) {
        char* sb = dynsm + (p % NSTG) * STAGE;
        const int kt = p << 5;
#pragma unroll
        for (int u = 0; u < 8; u++) {
            int c = tid + u * 256;                   // 0..2047
            bool isA = c < 1024;
            int idx = isA ? c : c - 1024;
            int row = idx >> 3, k16 = idx & 7;
            const float* src = isA
                ? (A + (size_t)(rowBase + row) * lda + kt + k16 * 4)
                : (B + (size_t)(colBase + row) * ldb + kt + k16 * 4);
            char* dst = sb + (isA ? 0 : AMAT_BYTES) + row * (ROWSTRIDE * 4) + k16 * 16;
            asm volatile("cp.async.cg.shared.global [%0], [%1], 16;"
                         :: "l"(dst), "l"(src) : "memory");
        }
        asm volatile("cp.async.commit_group;" ::: "memory");
    };

    float acc[4][4][4];
#pragma unroll
    for (int i = 0; i < 4; i++)
#pragma unroll
        for (int j = 0; j < 4; j++)
#pragma unroll
            for (int r = 0; r < 4; r++) acc[i][j][r] = 0.f;

    load_stage(0);
    load_stage(1);

    const int lr = lane >> 2, lk = lane & 3;
    for (int it = 0; it < iters; ++it) {
        asm volatile("cp.async.wait_group %0;" :: "n"(1) : "memory");
        __syncthreads();
        if (it + 2 < iters) load_stage(it + 2);
        else asm volatile("cp.async.commit_group;" ::: "memory");

        const uint32_t* As = (const uint32_t*)(dynsm + (it % NSTG) * STAGE);
        const uint32_t* Bs = As + 128 * ROWSTRIDE;
#pragma unroll
        for (int ks = 0; ks < 4; ks++) {
            const int k0 = ks * 8 + lk;
            uint32_t a[4][4], b[4][2];
#pragma unroll
            for (int mt = 0; mt < 4; mt++) {
                int r0 = wr * 64 + mt * 16 + lr;
                a[mt][0] = As[r0 * ROWSTRIDE + k0];
                a[mt][1] = As[(r0 + 8) * ROWSTRIDE + k0];
                a[mt][2] = As[r0 * ROWSTRIDE + k0 + 4];
                a[mt][3] = As[(r0 + 8) * ROWSTRIDE + k0 + 4];
            }
#pragma unroll
            for (int nt = 0; nt < 4; nt++) {
                int n0 = wc * 32 + nt * 8 + lr;
                b[nt][0] = Bs[n0 * ROWSTRIDE + k0];
                b[nt][1] = Bs[n0 * ROWSTRIDE + k0 + 4];
            }
#pragma unroll
            for (int mt = 0; mt < 4; mt++)
#pragma unroll
                for (int nt = 0; nt < 4; nt++)
                    MMA_TF32(acc[mt][nt], a[mt], b[nt]);
        }
        __syncthreads();
    }

    // ---- epilogue: stage through smem (reuse pipeline buffers), then store
    float* eps = (float*)dynsm;                      // [128][129]
    {
        const int rb = wr * 64 + lr;
        const int cb0 = wc * 32 + 2 * lk;
#pragma unroll
        for (int mt = 0; mt < 4; mt++)
#pragma unroll
            for (int nt = 0; nt < 4; nt++) {
                int r = rb + mt * 16, c = cb0 + nt * 8;
                eps[r * 129 + c]           = acc[mt][nt][0];
                eps[r * 129 + c + 1]       = acc[mt][nt][1];
                eps[(r + 8) * 129 + c]     = acc[mt][nt][2];
                eps[(r + 8) * 129 + c + 1] = acc[mt][nt][3];
            }
    }
    __syncthreads();

#pragma unroll 4
    for (int idx = tid; idx < 128 * 128; idx += 256) {
        if (EPI == 1) {
            int e = colBase + (idx >> 7);            // d_inner index
            int grow = rowBase + (idx & 127);        // global row in [0,8192)
            float v = rna(eps[(idx & 127) * 129 + (idx >> 7)] + bias[e]);
            Cb[(size_t)(grow >> 11) * DI * SEQ + (size_t)e * SEQ + (grow & 2047)] = v;
        } else {
            int r0 = idx >> 7, j = idx & 127;
            int row = rowBase + r0, col = colBase + j;
            float v = eps[r0 * 129 + j];
            if (EPI == 0) v = rna(phi_act(v + bias[col]));
            else if (EPI == 2) { if (bx == by && col > row) v = 0.f; v = rna(v); }
            else if (EPI == 3) v = rna(v / den[bz * SEQ + row]);
            else v += bias[col];
            (Cb + (size_t)bz * cB)[(size_t)row * ldc + col] = v;
        }
    }
}

// ---------------------------------------------------------------------------
extern "C" void kernel_launch(void* const* d_in, const int* in_sizes, int n_in,
                              void* d_out, int out_size)
{
    const float* x  = (const float*)d_in[0];
    const float* Wq = (const float*)d_in[1];
    const float* bq = (const float*)d_in[2];
    const float* Wk = (const float*)d_in[3];
    const float* bk = (const float*)d_in[4];
    const float* Wv = (const float*)d_in[5];
    const float* bv = (const float*)d_in[6];
    const float* Wo = (const float*)d_in[7];
    const float* bo = (const float*)d_in[8];
    float* out = (float*)d_out;

    float *xr, *Wqt, *Wkt, *Wvt, *Wot, *Qp, *Kp, *Vtp, *Sp, *Op, *dp;
    cudaGetSymbolAddress((void**)&xr,  g_xr);
    cudaGetSymbolAddress((void**)&Wqt, g_Wqt);
    cudaGetSymbolAddress((void**)&Wkt, g_Wkt);
    cudaGetSymbolAddress((void**)&Wvt, g_Wvt);
    cudaGetSymbolAddress((void**)&Wot, g_Wot);
    cudaGetSymbolAddress((void**)&Qp,  g_Q);
    cudaGetSymbolAddress((void**)&Kp,  g_K);
    cudaGetSymbolAddress((void**)&Vtp, g_Vt);
    cudaGetSymbolAddress((void**)&Sp,  g_S);
    cudaGetSymbolAddress((void**)&Op,  g_O);
    cudaGetSymbolAddress((void**)&dp,  g_den);

    const int DSM = NSTG * STAGE;                    // 110592
    cudaFuncSetAttribute(gemm_tc<0>, cudaFuncAttributeMaxDynamicSharedMemorySize, DSM);
    cudaFuncSetAttribute(gemm_tc<1>, cudaFuncAttributeMaxDynamicSharedMemorySize, DSM);
    cudaFuncSetAttribute(gemm_tc<2>, cudaFuncAttributeMaxDynamicSharedMemorySize, DSM);
    cudaFuncSetAttribute(gemm_tc<3>, cudaFuncAttributeMaxDynamicSharedMemorySize, DSM);
    cudaFuncSetAttribute(gemm_tc<4>, cudaFuncAttributeMaxDynamicSharedMemorySize, DSM);

    const int M = BATCH * SEQ;                       // 8192
    rna_copy4<<<M * DM / 4 / 256, 256>>>((const float4*)x, (float4*)xr, M * DM / 4);
    transpose_rna<<<dim3(DI / 32, DM / 32), dim3(32, 8)>>>(Wq, Wqt, DM, DI);
    transpose_rna<<<dim3(DI / 32, DM / 32), dim3(32, 8)>>>(Wk, Wkt, DM, DI);
    transpose_rna<<<dim3(DI / 32, DM / 32), dim3(32, 8)>>>(Wv, Wvt, DM, DI);
    transpose_rna<<<dim3(DM / 32, DI / 32), dim3(32, 8)>>>(Wo, Wot, DI, DM);

    dim3 gproj(DI / 128, M / 128, 1);                // (16,64)
    gemm_tc<0><<<gproj, 256, DSM>>>(xr, Wqt, bq, nullptr, Qp,  DM, DM, DI, DM, 0, 0, 0);
    gemm_tc<0><<<gproj, 256, DSM>>>(xr, Wkt, bk, nullptr, Kp,  DM, DM, DI, DM, 0, 0, 0);
    gemm_tc<1><<<gproj, 256, DSM>>>(xr, Wvt, bv, nullptr, Vtp, DM, DM, SEQ, DM, 0, 0, 0);

    dim3 gsc(SEQ / 128, SEQ / 128, BATCH);           // (16,16,4)
    gemm_tc<2><<<gsc, 256, DSM>>>(Qp, Kp, nullptr, nullptr, Sp, DI, DI, SEQ, DI,
                                  (long)SEQ * DI, (long)SEQ * DI, (long)SEQ * SEQ);

    rowsum_k<<<BATCH * SEQ, 256>>>(Sp, dp);

    dim3 gav(DI / 128, SEQ / 128, BATCH);            // (16,16,4)
    gemm_tc<3><<<gav, 256, DSM>>>(Sp, Vtp, nullptr, dp, Op, SEQ, SEQ, DI, SEQ,
                                  (long)SEQ * SEQ, (long)DI * SEQ, (long)SEQ * DI);

    dim3 gout(DM / 128, M / 128, 1);                 // (8,64)
    gemm_tc<4><<<gout, 256, DSM>>>(Op, Wot, bo, nullptr, out, DI, DI, DM, DI, 0, 0, 0);
}

// round 8
// speedup vs baseline: 3.2853x; 1.0816x over previous
#include <cuda_runtime.h>
#include <cstdint>
#include <math.h>

#define BATCH 4
#define SEQ   2048
#define DM    1024
#define DI    2048
#define NSTG  3
#define RS    36                              // row stride in floats (32 + 4 pad)
#define A_BYTES (128 * RS * 4)                // 18432
#define B_BYTES (256 * RS * 4)                // 36864
#define STAGE (A_BYTES + B_BYTES)             // 55296

__device__ __align__(16) float g_xr [BATCH * SEQ * DM];
__device__ __align__(16) float g_Wqt[DI * DM];
__device__ __align__(16) float g_Wkt[DI * DM];
__device__ __align__(16) float g_Wvt[DI * DM];
__device__ __align__(16) float g_Wot[DM * DI];
__device__ __align__(16) float g_Q  [BATCH * SEQ * DI];
__device__ __align__(16) float g_K  [BATCH * SEQ * DI];
__device__ __align__(16) float g_Vt [BATCH * DI * SEQ];
__device__ __align__(16) float g_S  [BATCH * SEQ * SEQ];
__device__ __align__(16) float g_O  [BATCH * SEQ * DI];
__device__ float g_den[BATCH * SEQ];

__device__ __forceinline__ float rna(float x) {
    uint32_t r;
    asm("cvt.rna.tf32.f32 %0, %1;" : "=r"(r) : "f"(x));
    return __uint_as_float(r);
}
__device__ __forceinline__ float phi_act(float v) { return v > 0.f ? v + 1.f : __expf(v); }

#define MMA_TF32(d, a, b)                                                     \
    asm volatile("mma.sync.aligned.m16n8k8.row.col.f32.tf32.tf32.f32 "        \
                 "{%0,%1,%2,%3}, {%4,%5,%6,%7}, {%8,%9}, {%0,%1,%2,%3};"      \
                 : "+f"((d)[0]), "+f"((d)[1]), "+f"((d)[2]), "+f"((d)[3])     \
                 : "r"((a)[0]), "r"((a)[1]), "r"((a)[2]), "r"((a)[3]),        \
                   "r"((b)[0]), "r"((b)[1]))

// ------------------------------- prep kernels -------------------------------
__global__ __launch_bounds__(256) void rna_copy4(
    const float4* __restrict__ in, float4* __restrict__ out, int n4)
{
    int i = blockIdx.x * 256 + threadIdx.x;
    if (i < n4) {
        float4 v = in[i];
        v.x = rna(v.x); v.y = rna(v.y); v.z = rna(v.z); v.w = rna(v.w);
        out[i] = v;
    }
}
// out[C,R] = rna(in[R,C]^T); grid (C/32, R/32, nmat), block (32,8)
__global__ __launch_bounds__(256) void transpose_rna3(
    const float* __restrict__ i0, const float* __restrict__ i1,
    const float* __restrict__ i2,
    float* __restrict__ o0, float* __restrict__ o1, float* __restrict__ o2,
    int R, int C)
{
    const float* in  = blockIdx.z == 0 ? i0 : (blockIdx.z == 1 ? i1 : i2);
    float*       out = blockIdx.z == 0 ? o0 : (blockIdx.z == 1 ? o1 : o2);
    __shared__ float t[32][33];
    int bx = blockIdx.x * 32, by = blockIdx.y * 32;
    int tx = threadIdx.x, ty = threadIdx.y;
#pragma unroll
    for (int j = 0; j < 32; j += 8)
        t[ty + j][tx] = in[(size_t)(by + ty + j) * C + bx + tx];
    __syncthreads();
#pragma unroll
    for (int j = 0; j < 32; j += 8)
        out[(size_t)(bx + ty + j) * R + by + tx] = rna(t[tx][ty + j]);
}

__global__ __launch_bounds__(256) void rowsum_k(
    const float* __restrict__ Sg, float* __restrict__ den)
{
    const int row = blockIdx.x;
    const int b = row >> 11, n = row & (SEQ - 1);
    const float* sr = Sg + ((size_t)b * SEQ + n) * SEQ;
    const int mlim = ((n >> 7) + 1) << 7;
    float s = 0.f;
    for (int m = threadIdx.x; m < mlim; m += 256) s += sr[m];
    __shared__ float red[256];
    red[threadIdx.x] = s;
    __syncthreads();
#pragma unroll
    for (int o = 128; o > 0; o >>= 1) {
        if (threadIdx.x < o) red[threadIdx.x] += red[threadIdx.x + o];
        __syncthreads();
    }
    if (threadIdx.x == 0) den[row] = red[0] + 1e-6f;
}

// ============================================================================
// tf32 mma.sync NT GEMM: C[M,N] = A[M,K]@B[N,K]^T + epilogue. Tile 128x256x32.
// 8 warps, each 64x64 (4x8 m16n8k8 tiles). 3-stage cp.async pipeline.
// EPI: 0=QKV merged (bz: 0/1 -> phi to C/C1, 2 -> bias + V^T to C2)
//      2=causal scores+rna  3=/den+rna  4=bias (output proj)
// ============================================================================
template <int EPI>
__global__ __launch_bounds__(256, 1) void gemm_tc(
    const float* __restrict__ Ab, const float* __restrict__ Bb,
    const float* __restrict__ bias, const float* __restrict__ den,
    float* __restrict__ Cb,
    int lda, int ldb, int ldc, int Kfull, long aB, long bB, long cB,
    const float* __restrict__ Bb1, const float* __restrict__ bias1,
    float* __restrict__ Cb1,
    const float* __restrict__ Bb2, const float* __restrict__ bias2,
    float* __restrict__ Cb2)
{
    const int bx = blockIdx.x, by = blockIdx.y, bz = blockIdx.z;
    if (EPI == 2 && 2 * bx > by) return;            // strictly-upper 256-wide block
    const int rowBase = by * 128, colBase = bx * 256;
    const int Klen = (EPI == 3) ? (by + 1) * 128 : Kfull;
    const int iters = Klen >> 5;                    // >= 4 always

    const float* A = Ab + (size_t)(EPI == 0 ? 0 : bz) * aB;
    const float* B;
    const float* bia;
    if (EPI == 0) {
        B   = bz == 0 ? Bb : (bz == 1 ? Bb1 : Bb2);
        bia = bz == 0 ? bias : (bz == 1 ? bias1 : bias2);
    } else {
        B = Bb + (size_t)bz * bB;
        bia = bias;
    }

    extern __shared__ char dynsm[];
    const int tid = threadIdx.x;
    const int lane = tid & 31, wid = tid >> 5;
    const int wr = wid & 1, wc = wid >> 1;          // warp owns 64x64

    auto load_stage = [&](int p) {
        char* sb = dynsm + (p % NSTG) * STAGE;
        const int kt = p << 5;
#pragma unroll
        for (int u = 0; u < 12; u++) {
            int c = tid + u * 256;                  // 0..3071
            bool isA = c < 1024;
            int idx = isA ? c : c - 1024;
            int row = idx >> 3, k16 = idx & 7;
            const float* src = isA
                ? (A + (size_t)(rowBase + row) * lda + kt + k16 * 4)
                : (B + (size_t)(colBase + row) * ldb + kt + k16 * 4);
            char* dst = sb + (isA ? 0 : A_BYTES) + row * (RS * 4) + k16 * 16;
            asm volatile("cp.async.cg.shared.global [%0], [%1], 16;"
                         :: "l"(dst), "l"(src) : "memory");
        }
        asm volatile("cp.async.commit_group;" ::: "memory");
    };

    float acc[4][8][4];
#pragma unroll
    for (int i = 0; i < 4; i++)
#pragma unroll
        for (int j = 0; j < 8; j++)
#pragma unroll
            for (int r = 0; r < 4; r++) acc[i][j][r] = 0.f;

    load_stage(0);
    load_stage(1);

    const int lr = lane >> 2, lk = lane & 3;
    for (int it = 0; it < iters; ++it) {
        asm volatile("cp.async.wait_group %0;" :: "n"(1) : "memory");
        __syncthreads();
        if (it + 2 < iters) load_stage(it + 2);
        else asm volatile("cp.async.commit_group;" ::: "memory");

        const uint32_t* As = (const uint32_t*)(dynsm + (it % NSTG) * STAGE);
        const uint32_t* Bs = As + 128 * RS;
#pragma unroll
        for (int ks = 0; ks < 4; ks++) {
            const int k0 = ks * 8 + lk;
            uint32_t a[4][4], b[8][2];
#pragma unroll
            for (int mt = 0; mt < 4; mt++) {
                int r0 = wr * 64 + mt * 16 + lr;
                a[mt][0] = As[r0 * RS + k0];
                a[mt][1] = As[(r0 + 8) * RS + k0];
                a[mt][2] = As[r0 * RS + k0 + 4];
                a[mt][3] = As[(r0 + 8) * RS + k0 + 4];
            }
#pragma unroll
            for (int nt = 0; nt < 8; nt++) {
                int n0 = wc * 64 + nt * 8 + lr;
                b[nt][0] = Bs[n0 * RS + k0];
                b[nt][1] = Bs[n0 * RS + k0 + 4];
            }
#pragma unroll
            for (int mt = 0; mt < 4; mt++)
#pragma unroll
                for (int nt = 0; nt < 8; nt++)
                    MMA_TF32(acc[mt][nt], a[mt], b[nt]);
        }
        __syncthreads();
    }

    // ---- epilogue: stage through smem, then store coalesced
    float* eps = (float*)dynsm;                     // [128][257]
    {
        const int rb = wr * 64 + lr;
        const int cb0 = wc * 64 + 2 * lk;
#pragma unroll
        for (int mt = 0; mt < 4; mt++)
#pragma unroll
            for (int nt = 0; nt < 8; nt++) {
                int r = rb + mt * 16, c = cb0 + nt * 8;
                eps[r * 257 + c]           = acc[mt][nt][0];
                eps[r * 257 + c + 1]       = acc[mt][nt][1];
                eps[(r + 8) * 257 + c]     = acc[mt][nt][2];
                eps[(r + 8) * 257 + c + 1] = acc[mt][nt][3];
            }
    }
    __syncthreads();

    const bool vpath = (EPI == 0 && bz == 2);
#pragma unroll 4
    for (int idx = tid; idx < 128 * 256; idx += 256) {
        if (vpath) {
            int e = colBase + (idx >> 7);           // d_inner index (0..255 local)
            int grow = rowBase + (idx & 127);       // global row in [0,8192)
            float v = rna(eps[(idx & 127) * 257 + (idx >> 7)] + bia[e]);
            Cb2[(size_t)(grow >> 11) * DI * SEQ + (size_t)e * SEQ + (grow & 2047)] = v;
        } else {
            int r0 = idx >> 8, j = idx & 255;
            int row = rowBase + r0, col = colBase + j;
            float v = eps[r0 * 257 + j];
            if (EPI == 0) {
                v = rna(phi_act(v + bia[col]));
                float* Cd = (bz == 0) ? Cb : Cb1;
                Cd[(size_t)row * ldc + col] = v;
            } else {
                if (EPI == 2) { if (bx == (by >> 1) && col > row) v = 0.f; v = rna(v); }
                else if (EPI == 3) v = rna(v / den[bz * SEQ + row]);
                else v += bia[col];
                (Cb + (size_t)bz * cB)[(size_t)row * ldc + col] = v;
            }
        }
    }
}

// ---------------------------------------------------------------------------
extern "C" void kernel_launch(void* const* d_in, const int* in_sizes, int n_in,
                              void* d_out, int out_size)
{
    const float* x  = (const float*)d_in[0];
    const float* Wq = (const float*)d_in[1];
    const float* bq = (const float*)d_in[2];
    const float* Wk = (const float*)d_in[3];
    const float* bk = (const float*)d_in[4];
    const float* Wv = (const float*)d_in[5];
    const float* bv = (const float*)d_in[6];
    const float* Wo = (const float*)d_in[7];
    const float* bo = (const float*)d_in[8];
    float* out = (float*)d_out;

    float *xr, *Wqt, *Wkt, *Wvt, *Wot, *Qp, *Kp, *Vtp, *Sp, *Op, *dp;
    cudaGetSymbolAddress((void**)&xr,  g_xr);
    cudaGetSymbolAddress((void**)&Wqt, g_Wqt);
    cudaGetSymbolAddress((void**)&Wkt, g_Wkt);
    cudaGetSymbolAddress((void**)&Wvt, g_Wvt);
    cudaGetSymbolAddress((void**)&Wot, g_Wot);
    cudaGetSymbolAddress((void**)&Qp,  g_Q);
    cudaGetSymbolAddress((void**)&Kp,  g_K);
    cudaGetSymbolAddress((void**)&Vtp, g_Vt);
    cudaGetSymbolAddress((void**)&Sp,  g_S);
    cudaGetSymbolAddress((void**)&Op,  g_O);
    cudaGetSymbolAddress((void**)&dp,  g_den);

    const int DSM = NSTG * STAGE;                   // 165888
    cudaFuncSetAttribute(gemm_tc<0>, cudaFuncAttributeMaxDynamicSharedMemorySize, DSM);
    cudaFuncSetAttribute(gemm_tc<2>, cudaFuncAttributeMaxDynamicSharedMemorySize, DSM);
    cudaFuncSetAttribute(gemm_tc<3>, cudaFuncAttributeMaxDynamicSharedMemorySize, DSM);
    cudaFuncSetAttribute(gemm_tc<4>, cudaFuncAttributeMaxDynamicSharedMemorySize, DSM);

    const int M = BATCH * SEQ;                      // 8192
    rna_copy4<<<M * DM / 4 / 256, 256>>>((const float4*)x, (float4*)xr, M * DM / 4);
    transpose_rna3<<<dim3(DI / 32, DM / 32, 3), dim3(32, 8)>>>(
        Wq, Wk, Wv, Wqt, Wkt, Wvt, DM, DI);
    transpose_rna3<<<dim3(DM / 32, DI / 32, 1), dim3(32, 8)>>>(
        Wo, Wo, Wo, Wot, Wot, Wot, DI, DM);

    // fused Q/K/V projection: grid z selects weight
    dim3 gqkv(DI / 256, M / 128, 3);                // (8,64,3)
    gemm_tc<0><<<gqkv, 256, DSM>>>(xr, Wqt, bq, nullptr, Qp, DM, DM, DI, DM, 0, 0, 0,
                                   Wkt, bk, Kp, Wvt, bv, Vtp);

    dim3 gsc(SEQ / 256, SEQ / 128, BATCH);          // (8,16,4)
    gemm_tc<2><<<gsc, 256, DSM>>>(Qp, Kp, nullptr, nullptr, Sp, DI, DI, SEQ, DI,
                                  (long)SEQ * DI, (long)SEQ * DI, (long)SEQ * SEQ,
                                  nullptr, nullptr, nullptr, nullptr, nullptr, nullptr);

    rowsum_k<<<BATCH * SEQ, 256>>>(Sp, dp);

    dim3 gav(DI / 256, SEQ / 128, BATCH);           // (8,16,4)
    gemm_tc<3><<<gav, 256, DSM>>>(Sp, Vtp, nullptr, dp, Op, SEQ, SEQ, DI, SEQ,
                                  (long)SEQ * SEQ, (long)DI * SEQ, (long)SEQ * DI,
                                  nullptr, nullptr, nullptr, nullptr, nullptr, nullptr);

    dim3 gout(DM / 256, M / 128, 1);                // (4,64)
    gemm_tc<4><<<gout, 256, DSM>>>(Op, Wot, bo, nullptr, out, DI, DI, DM, DI, 0, 0, 0,
                                   nullptr, nullptr, nullptr, nullptr, nullptr, nullptr);
}

// round 9
// speedup vs baseline: 5.8590x; 1.7834x over previous
#include <cuda_runtime.h>
#include <cuda_fp16.h>
#include <cstdint>
#include <math.h>

#define BATCH 4
#define SEQ   2048
#define DM    1024
#define DI    2048
#define NSTG  3
#define ROWB  144                      // bytes per 64-half row (128B data + 16B pad)
#define A_BYTES (128 * ROWB)           // 18432
#define B_BYTES (256 * ROWB)           // 36864
#define STAGE (A_BYTES + B_BYTES)      // 55296

__device__ __align__(16) __half g_xh [BATCH * SEQ * DM];
__device__ __align__(16) __half g_Wqt[DI * DM];
__device__ __align__(16) __half g_Wkt[DI * DM];
__device__ __align__(16) __half g_Wvt[DI * DM];
__device__ __align__(16) __half g_Wot[DM * DI];
__device__ __align__(16) __half g_Q  [BATCH * SEQ * DI];
__device__ __align__(16) __half g_K  [BATCH * SEQ * DI];
__device__ __align__(16) __half g_Vt [BATCH * DI * SEQ];
__device__ __align__(16) __half g_S  [BATCH * SEQ * SEQ];
__device__ __align__(16) __half g_O  [BATCH * SEQ * DI];
__device__ float g_den[BATCH * SEQ];

__device__ __forceinline__ uint32_t smem_u32(const void* p) {
    uint32_t a;
    asm("{ .reg .u64 t; cvta.to.shared.u64 t, %1; cvt.u32.u64 %0, t; }" : "=r"(a) : "l"(p));
    return a;
}
__device__ __forceinline__ float phi_act(float v) { return v > 0.f ? v + 1.f : __expf(v); }

#define LDMX4(r0, r1, r2, r3, addr)                                           \
    asm volatile("ldmatrix.sync.aligned.m8n8.x4.shared.b16 {%0,%1,%2,%3}, [%4];" \
                 : "=r"(r0), "=r"(r1), "=r"(r2), "=r"(r3) : "r"(addr))

#define MMA_F16(d, a, b0, b1)                                                 \
    asm volatile("mma.sync.aligned.m16n8k16.row.col.f32.f16.f16.f32 "         \
                 "{%0,%1,%2,%3}, {%4,%5,%6,%7}, {%8,%9}, {%0,%1,%2,%3};"      \
                 : "+f"((d)[0]), "+f"((d)[1]), "+f"((d)[2]), "+f"((d)[3])     \
                 : "r"((a)[0]), "r"((a)[1]), "r"((a)[2]), "r"((a)[3]),        \
                   "r"(b0), "r"(b1))

// ------------------------------- prep kernels -------------------------------
__global__ __launch_bounds__(256) void f2h4(
    const float4* __restrict__ in, __half2* __restrict__ out, int n4)
{
    int i = blockIdx.x * 256 + threadIdx.x;
    if (i < n4) {
        float4 v = in[i];
        out[2 * i]     = __floats2half2_rn(v.x, v.y);
        out[2 * i + 1] = __floats2half2_rn(v.z, v.w);
    }
}
// out[C,R] = half(in[R,C]^T); grid (C/32, R/32, nmat), block (32,8)
__global__ __launch_bounds__(256) void transpose_h3(
    const float* __restrict__ i0, const float* __restrict__ i1,
    const float* __restrict__ i2,
    __half* __restrict__ o0, __half* __restrict__ o1, __half* __restrict__ o2,
    int R, int C)
{
    const float* in = blockIdx.z == 0 ? i0 : (blockIdx.z == 1 ? i1 : i2);
    __half*     out = blockIdx.z == 0 ? o0 : (blockIdx.z == 1 ? o1 : o2);
    __shared__ float t[32][33];
    int bx = blockIdx.x * 32, by = blockIdx.y * 32;
    int tx = threadIdx.x, ty = threadIdx.y;
#pragma unroll
    for (int j = 0; j < 32; j += 8)
        t[ty + j][tx] = in[(size_t)(by + ty + j) * C + bx + tx];
    __syncthreads();
#pragma unroll
    for (int j = 0; j < 32; j += 8)
        out[(size_t)(bx + ty + j) * R + by + tx] = __float2half_rn(t[tx][ty + j]);
}

__global__ __launch_bounds__(256) void rowsum_k(
    const __half* __restrict__ Sg, float* __restrict__ den)
{
    const int row = blockIdx.x;
    const int b = row >> 11, n = row & (SEQ - 1);
    const __half* sr = Sg + ((size_t)b * SEQ + n) * SEQ;
    const int mlim = ((n >> 7) + 1) << 7;
    float s = 0.f;
    for (int m = threadIdx.x; m < mlim; m += 256) s += __half2float(sr[m]);
    __shared__ float red[256];
    red[threadIdx.x] = s;
    __syncthreads();
#pragma unroll
    for (int o = 128; o > 0; o >>= 1) {
        if (threadIdx.x < o) red[threadIdx.x] += red[threadIdx.x + o];
        __syncthreads();
    }
    if (threadIdx.x == 0) den[row] = red[0] + 1e-6f;
}

// ============================================================================
// fp16 mma.sync NT GEMM: C = A[M,K]@B[N,K]^T + epilogue. Tile 128x256x64.
// 8 warps, each 64x64 (4x8 of m16n8k16). ldmatrix fragments, 3-stage cp.async.
// EPI: 0=QKV merged (bz: 0/1 -> phi half, 2 -> bias + V^T half)
//      2=causal scores half  3=/den half  4=bias float (output proj)
// ============================================================================
template <int EPI>
__global__ __launch_bounds__(256, 1) void gemm_h(
    const __half* __restrict__ Ab, const __half* __restrict__ Bb,
    const float* __restrict__ bias, const float* __restrict__ den,
    __half* __restrict__ Ch,
    int lda, int ldb, int ldc, int Kfull, long aB, long bB, long cB,
    const __half* __restrict__ Bb1, const float* __restrict__ bias1,
    __half* __restrict__ Ch1,
    const __half* __restrict__ Bb2, const float* __restrict__ bias2,
    __half* __restrict__ Ch2,
    float* __restrict__ Cf)
{
    const int bx = blockIdx.x, by = blockIdx.y, bz = blockIdx.z;
    if (EPI == 2 && 2 * bx > by) return;
    const int rowBase = by * 128, colBase = bx * 256;
    const int Klen = (EPI == 3) ? (by + 1) * 128 : Kfull;
    const int iters = Klen >> 6;

    const __half* A = Ab + (size_t)(EPI == 0 ? 0 : bz) * aB;
    const __half* B;
    const float* bia;
    if (EPI == 0) {
        B   = bz == 0 ? Bb : (bz == 1 ? Bb1 : Bb2);
        bia = bz == 0 ? bias : (bz == 1 ? bias1 : bias2);
    } else {
        B = Bb + (size_t)bz * bB;
        bia = bias;
    }

    extern __shared__ char dynsm[];
    const int tid = threadIdx.x;
    const int lane = tid & 31, wid = tid >> 5;
    const int wr = wid & 1, wc = wid >> 1;           // warp owns 64x64
    const uint32_t smBase = smem_u32(dynsm);

    auto load_stage = [&](int p) {
        char* sb = dynsm + (p % NSTG) * STAGE;
        const int kt = p << 6;
#pragma unroll
        for (int u = 0; u < 12; u++) {
            int c = tid + u * 256;                   // 0..3071 chunks of 16B (8 halfs)
            bool isA = c < 1024;
            int idx = isA ? c : c - 1024;
            int row = idx >> 3, ch = idx & 7;
            const __half* src = isA
                ? (A + (size_t)(rowBase + row) * lda + kt + ch * 8)
                : (B + (size_t)(colBase + row) * ldb + kt + ch * 8);
            char* dst = sb + (isA ? 0 : A_BYTES) + row * ROWB + ch * 16;
            asm volatile("cp.async.cg.shared.global [%0], [%1], 16;"
                         :: "l"(dst), "l"(src) : "memory");
        }
        asm volatile("cp.async.commit_group;" ::: "memory");
    };

    float acc[4][8][4];
#pragma unroll
    for (int i = 0; i < 4; i++)
#pragma unroll
        for (int j = 0; j < 8; j++)
#pragma unroll
            for (int r = 0; r < 4; r++) acc[i][j][r] = 0.f;

    load_stage(0);
    load_stage(1);

    // ldmatrix lane->address components
    const int laneRA = (lane & 7) + ((lane >> 3) & 1) * 8;   // A: row offset
    const int laneKA = (lane >> 4) * 8;                      // A: k offset (halfs)
    const int laneRB = (lane & 7) + (lane >> 4) * 8;         // B: row offset
    const int laneKB = ((lane >> 3) & 1) * 8;                // B: k offset

    for (int it = 0; it < iters; ++it) {
        asm volatile("cp.async.wait_group %0;" :: "n"(1) : "memory");
        __syncthreads();
        if (it + 2 < iters) load_stage(it + 2);
        else asm volatile("cp.async.commit_group;" ::: "memory");

        const uint32_t smA = smBase + (it % NSTG) * STAGE;
        const uint32_t smB = smA + A_BYTES;
        const uint32_t aBase = smA + (uint32_t)(wr * 64 + laneRA) * ROWB + laneKA * 2;
        const uint32_t bBase = smB + (uint32_t)(wc * 64 + laneRB) * ROWB + laneKB * 2;

#pragma unroll
        for (int ks = 0; ks < 4; ks++) {
            const uint32_t kOff = ks * 32;           // 16 halfs = 32 bytes
            uint32_t a[4][4], b[4][4];
#pragma unroll
            for (int mt = 0; mt < 4; mt++)
                LDMX4(a[mt][0], a[mt][1], a[mt][2], a[mt][3],
                      aBase + (uint32_t)mt * 16 * ROWB + kOff);
#pragma unroll
            for (int p = 0; p < 4; p++)
                LDMX4(b[p][0], b[p][1], b[p][2], b[p][3],
                      bBase + (uint32_t)p * 16 * ROWB + kOff);
#pragma unroll
            for (int mt = 0; mt < 4; mt++)
#pragma unroll
                for (int nt = 0; nt < 8; nt++) {
                    const int pr = nt >> 1, od = (nt & 1) * 2;
                    MMA_F16(acc[mt][nt], a[mt], b[pr][od], b[pr][od + 1]);
                }
        }
        __syncthreads();
    }

    // ---- epilogue: stage through smem (float), then store coalesced
    float* eps = (float*)dynsm;                      // [128][257]
    {
        const int lr = lane >> 2, lk = lane & 3;
        const int rb = wr * 64 + lr;
        const int cb0 = wc * 64 + 2 * lk;
#pragma unroll
        for (int mt = 0; mt < 4; mt++)
#pragma unroll
            for (int nt = 0; nt < 8; nt++) {
                int r = rb + mt * 16, c = cb0 + nt * 8;
                eps[r * 257 + c]           = acc[mt][nt][0];
                eps[r * 257 + c + 1]       = acc[mt][nt][1];
                eps[(r + 8) * 257 + c]     = acc[mt][nt][2];
                eps[(r + 8) * 257 + c + 1] = acc[mt][nt][3];
            }
    }
    __syncthreads();

    const bool vpath = (EPI == 0 && bz == 2);
#pragma unroll 4
    for (int idx = tid; idx < 128 * 256; idx += 256) {
        if (vpath) {
            int e = colBase + (idx >> 7);            // d_inner index
            int grow = rowBase + (idx & 127);        // global row in [0,8192)
            float v = eps[(idx & 127) * 257 + (idx >> 7)] + bia[e];
            Ch2[(size_t)(grow >> 11) * DI * SEQ + (size_t)e * SEQ + (grow & 2047)] =
                __float2half_rn(v);
        } else {
            int r0 = idx >> 8, j = idx & 255;
            int row = rowBase + r0, col = colBase + j;
            float v = eps[r0 * 257 + j];
            if (EPI == 0) {
                __half* Cd = (bz == 0) ? Ch : Ch1;
                Cd[(size_t)row * ldc + col] = __float2half_rn(phi_act(v + bia[col]));
            } else if (EPI == 2) {
                if (bx == (by >> 1) && col > row) v = 0.f;
                (Ch + (size_t)bz * cB)[(size_t)row * ldc + col] = __float2half_rn(v);
            } else if (EPI == 3) {
                v /= den[bz * SEQ + row];
                (Ch + (size_t)bz * cB)[(size_t)row * ldc + col] = __float2half_rn(v);
            } else {
                Cf[(size_t)row * ldc + col] = v + bia[col];
            }
        }
    }
}

// ---------------------------------------------------------------------------
extern "C" void kernel_launch(void* const* d_in, const int* in_sizes, int n_in,
                              void* d_out, int out_size)
{
    const float* x  = (const float*)d_in[0];
    const float* Wq = (const float*)d_in[1];
    const float* bq = (const float*)d_in[2];
    const float* Wk = (const float*)d_in[3];
    const float* bk = (const float*)d_in[4];
    const float* Wv = (const float*)d_in[5];
    const float* bv = (const float*)d_in[6];
    const float* Wo = (const float*)d_in[7];
    const float* bo = (const float*)d_in[8];
    float* out = (float*)d_out;

    __half *xh, *Wqt, *Wkt, *Wvt, *Wot, *Qp, *Kp, *Vtp, *Sp, *Op;
    float* dp;
    cudaGetSymbolAddress((void**)&xh,  g_xh);
    cudaGetSymbolAddress((void**)&Wqt, g_Wqt);
    cudaGetSymbolAddress((void**)&Wkt, g_Wkt);
    cudaGetSymbolAddress((void**)&Wvt, g_Wvt);
    cudaGetSymbolAddress((void**)&Wot, g_Wot);
    cudaGetSymbolAddress((void**)&Qp,  g_Q);
    cudaGetSymbolAddress((void**)&Kp,  g_K);
    cudaGetSymbolAddress((void**)&Vtp, g_Vt);
    cudaGetSymbolAddress((void**)&Sp,  g_S);
    cudaGetSymbolAddress((void**)&Op,  g_O);
    cudaGetSymbolAddress((void**)&dp,  g_den);

    const int DSM = NSTG * STAGE;                    // 165888
    cudaFuncSetAttribute(gemm_h<0>, cudaFuncAttributeMaxDynamicSharedMemorySize, DSM);
    cudaFuncSetAttribute(gemm_h<2>, cudaFuncAttributeMaxDynamicSharedMemorySize, DSM);
    cudaFuncSetAttribute(gemm_h<3>, cudaFuncAttributeMaxDynamicSharedMemorySize, DSM);
    cudaFuncSetAttribute(gemm_h<4>, cudaFuncAttributeMaxDynamicSharedMemorySize, DSM);

    const int M = BATCH * SEQ;                       // 8192
    f2h4<<<M * DM / 4 / 256, 256>>>((const float4*)x, (__half2*)xh, M * DM / 4);
    transpose_h3<<<dim3(DI / 32, DM / 32, 3), dim3(32, 8)>>>(
        Wq, Wk, Wv, Wqt, Wkt, Wvt, DM, DI);
    transpose_h3<<<dim3(DM / 32, DI / 32, 1), dim3(32, 8)>>>(
        Wo, Wo, Wo, Wot, Wot, Wot, DI, DM);

    // fused Q/K/V projection: grid z selects weight
    dim3 gqkv(DI / 256, M / 128, 3);                 // (8,64,3)
    gemm_h<0><<<gqkv, 256, DSM>>>(xh, Wqt, bq, nullptr, Qp, DM, DM, DI, DM, 0, 0, 0,
                                  Wkt, bk, Kp, Wvt, bv, Vtp, nullptr);

    dim3 gsc(SEQ / 256, SEQ / 128, BATCH);           // (8,16,4)
    gemm_h<2><<<gsc, 256, DSM>>>(Qp, Kp, nullptr, nullptr, Sp, DI, DI, SEQ, DI,
                                 (long)SEQ * DI, (long)SEQ * DI, (long)SEQ * SEQ,
                                 nullptr, nullptr, nullptr, nullptr, nullptr, nullptr,
                                 nullptr);

    rowsum_k<<<BATCH * SEQ, 256>>>(Sp, dp);

    dim3 gav(DI / 256, SEQ / 128, BATCH);            // (8,16,4)
    gemm_h<3><<<gav, 256, DSM>>>(Sp, Vtp, nullptr, dp, Op, SEQ, SEQ, DI, SEQ,
                                 (long)SEQ * SEQ, (long)DI * SEQ, (long)SEQ * DI,
                                 nullptr, nullptr, nullptr, nullptr, nullptr, nullptr,
                                 nullptr);

    dim3 gout(DM / 256, M / 128, 1);                 // (4,64)
    gemm_h<4><<<gout, 256, DSM>>>(Op, Wot, bo, nullptr, nullptr, DI, DI, DM, DI, 0, 0, 0,
                                  nullptr, nullptr, nullptr, nullptr, nullptr, nullptr,
                                  out);
}